// round 11
// baseline (speedup 1.0000x reference)
#include <cuda_runtime.h>
#include <cstdint>

// Problem constants
#define BATCH 2
#define NCAM  6
#define DD    48
#define HH    28
#define WW    60
#define CC    64
#define GX    128
#define GY    128
#define NTILE (GX / 32)          // 4 tiles of 32 x per row
#define NTILES (BATCH * GY * NTILE)  // 1024

// Per-(b,cam) projection matrix M (3x4): uvd = M @ [gx,gy,gz,1]
__device__ float    g_M[BATCH * NCAM * 12];
// Per-tile 24-bit validity mask (combo = cam*4 + z)
__device__ unsigned g_mask[NTILES];

// ---------------------------------------------------------------------------
// Prep kernel: grid 64 x 512 threads; one warp per BEV tile.
// Each warp: all 32 lanes redundantly compute M = K @ inv(l2s)[0:3,:] for
// matrix index min(lane,23) (SIMT: full chain once); then lanes 0..23 run the
// exact divide-free interval test for combo = lane on this warp's tile,
// pulling the right matrix via per-lane shuffles. Ballot -> g_mask[tile].
// Block 0 / warp 0 additionally writes g_M.
// ---------------------------------------------------------------------------
__global__ void __launch_bounds__(512)
prep_kernel(const float* __restrict__ intr,
            const float* __restrict__ l2s) {
    const int lane = threadIdx.x & 31;
    const int w    = threadIdx.x >> 5;
    const int tile = blockIdx.x * 16 + w;          // 0..1023
    const int b    = tile / (GY * NTILE);
    const int rem  = tile - b * (GY * NTILE);
    const int y    = rem >> 2;                     // NTILE == 4
    const int bx   = rem & 3;

    // ---- per-lane matrix: index = min(lane, 23) ----
    const int idxL = lane < 24 ? lane : 23;
    const float* m = l2s + idxL * 16;   // row-major 4x4
    const float* K = intr + idxL * 9;   // row-major 3x3

    float inv[16];
    inv[0]  =  m[5]*m[10]*m[15] - m[5]*m[11]*m[14] - m[9]*m[6]*m[15] + m[9]*m[7]*m[14] + m[13]*m[6]*m[11] - m[13]*m[7]*m[10];
    inv[4]  = -m[4]*m[10]*m[15] + m[4]*m[11]*m[14] + m[8]*m[6]*m[15] - m[8]*m[7]*m[14] - m[12]*m[6]*m[11] + m[12]*m[7]*m[10];
    inv[8]  =  m[4]*m[9]*m[15]  - m[4]*m[11]*m[13] - m[8]*m[5]*m[15] + m[8]*m[7]*m[13] + m[12]*m[5]*m[11] - m[12]*m[7]*m[9];
    inv[12] = -m[4]*m[9]*m[14]  + m[4]*m[10]*m[13] + m[8]*m[5]*m[14] - m[8]*m[6]*m[13] - m[12]*m[5]*m[10] + m[12]*m[6]*m[9];
    inv[1]  = -m[1]*m[10]*m[15] + m[1]*m[11]*m[14] + m[9]*m[2]*m[15] - m[9]*m[3]*m[14] - m[13]*m[2]*m[11] + m[13]*m[3]*m[10];
    inv[5]  =  m[0]*m[10]*m[15] - m[0]*m[11]*m[14] - m[8]*m[2]*m[15] + m[8]*m[3]*m[14] + m[12]*m[2]*m[11] - m[12]*m[3]*m[10];
    inv[9]  = -m[0]*m[9]*m[15]  + m[0]*m[11]*m[13] + m[8]*m[1]*m[15] - m[8]*m[3]*m[13] - m[12]*m[1]*m[11] + m[12]*m[3]*m[9];
    inv[13] =  m[0]*m[9]*m[14]  - m[0]*m[10]*m[13] - m[8]*m[1]*m[14] + m[8]*m[2]*m[13] + m[12]*m[1]*m[10] - m[12]*m[2]*m[9];
    inv[2]  =  m[1]*m[6]*m[15]  - m[1]*m[7]*m[14]  - m[5]*m[2]*m[15] + m[5]*m[3]*m[14] + m[13]*m[2]*m[7]  - m[13]*m[3]*m[6];
    inv[6]  = -m[0]*m[6]*m[15]  + m[0]*m[7]*m[14]  + m[4]*m[2]*m[15] - m[4]*m[3]*m[14] - m[12]*m[2]*m[7]  + m[12]*m[3]*m[6];
    inv[10] =  m[0]*m[5]*m[15]  - m[0]*m[7]*m[13]  - m[4]*m[1]*m[15] + m[4]*m[3]*m[13] + m[12]*m[1]*m[7]  - m[12]*m[3]*m[5];
    inv[14] = -m[0]*m[5]*m[14]  + m[0]*m[6]*m[13]  + m[4]*m[1]*m[14] - m[4]*m[2]*m[13] - m[12]*m[1]*m[6]  + m[12]*m[2]*m[5];
    inv[3]  = -m[1]*m[6]*m[11]  + m[1]*m[7]*m[10]  + m[5]*m[2]*m[11] - m[5]*m[3]*m[10] - m[9]*m[2]*m[7]   + m[9]*m[3]*m[6];
    inv[7]  =  m[0]*m[6]*m[11]  - m[0]*m[7]*m[10]  - m[4]*m[2]*m[11] + m[4]*m[3]*m[10] + m[8]*m[2]*m[7]   - m[8]*m[3]*m[6];
    inv[11] = -m[0]*m[5]*m[11]  + m[0]*m[7]*m[9]   + m[4]*m[1]*m[11] - m[4]*m[3]*m[9]  - m[8]*m[1]*m[7]   + m[8]*m[3]*m[5];
    inv[15] =  m[0]*m[5]*m[10]  - m[0]*m[6]*m[9]   - m[4]*m[1]*m[10] + m[4]*m[2]*m[9]  + m[8]*m[1]*m[6]   - m[8]*m[2]*m[5];

    float det = m[0]*inv[0] + m[1]*inv[4] + m[2]*inv[8] + m[3]*inv[12];
    float rdet = 1.0f / det;
    #pragma unroll
    for (int i = 0; i < 16; i++) inv[i] *= rdet;

    float Mr[12];
    #pragma unroll
    for (int r = 0; r < 3; r++) {
        #pragma unroll
        for (int c = 0; c < 4; c++) {
            Mr[r * 4 + c] = K[r*3 + 0] * inv[0*4 + c]
                          + K[r*3 + 1] * inv[1*4 + c]
                          + K[r*3 + 2] * inv[2*4 + c];
        }
    }
    if (blockIdx.x == 0 && w == 0 && lane < 24) {
        #pragma unroll
        for (int i = 0; i < 12; i++) g_M[lane * 12 + i] = Mr[i];
    }

    // ---- exact interval validity test: lanes 0..23, combo = lane ----
    const int cam = lane >> 2;                       // for lane < 24
    const int j   = b * NCAM + (cam < 6 ? cam : 0);  // matrix index for this tile
    float Ms[12];
    #pragma unroll
    for (int i = 0; i < 12; i++)
        Ms[i] = __shfl_sync(0xffffffffu, Mr[i], j);

    int pass = 0;
    if (lane < 24) {
        const int zz = lane & 3;
        const float gz  = -3.0f + 2.0f * (float)zz;
        const float gy  = -47.625f + 0.75f * (float)y;
        const float gxa = -47.625f + 0.75f * (float)(bx * 32);
        const float gxb = -47.625f + 0.75f * (float)(bx * 32 + 31);
        const float DLO = 0.9770f;   // d > 2 - 48/47, widened down
        const float DHI = 51.05f;    // d < 2 + 48*48/47, widened up
        const float uc = Ms[1]*gy + Ms[2]*gz  + Ms[3];
        const float vc = Ms[5]*gy + Ms[6]*gz  + Ms[7];
        const float dc = Ms[9]*gy + Ms[10]*gz + Ms[11];
        float u0 = Ms[0]*gxa + uc, u1 = Ms[0]*gxb + uc;
        float v0 = Ms[4]*gxa + vc, v1 = Ms[4]*gxb + vc;
        float d0 = Ms[8]*gxa + dc, d1 = Ms[8]*gxb + dc;
        const float dmin = fminf(d0, d1), dmax = fmaxf(d0, d1);
        if (dmax > DLO && dmin < DHI) {
            if (dmin < DLO) {
                // d crosses DLO inside the tile; affine => exact crossing.
                const float t  = (DLO - d0) / (d1 - d0);
                const float uX = u0 + t * (u1 - u0);
                const float vX = v0 + t * (v1 - v0);
                if (d0 < DLO) { u0 = uX; v0 = vX; d0 = DLO; }
                else          { u1 = uX; v1 = vX; d1 = DLO; }
            }
            // d > 0 on (sub)interval: multiply bounds through by d (affine,
            // endpoint-exact). Margins live at zero-weight boundaries.
            const float sx = 59.0f / 60.0f, sy = 27.0f / 28.0f;
            const float a0 = sx * u0, a1 = sx * u1;
            const float e0 = sy * v0, e1 = sy * v1;
            const bool rej =
                (fmaxf(a0 + 1.002f  * d0, a1 + 1.002f  * d1) <= 0.0f) ||
                (fminf(a0 - 60.002f * d0, a1 - 60.002f * d1) >= 0.0f) ||
                (fmaxf(e0 + 1.002f  * d0, e1 + 1.002f  * d1) <= 0.0f) ||
                (fminf(e0 - 28.002f * d0, e1 - 28.002f * d1) >= 0.0f);
            pass = !rej;
        }
    }
    const unsigned ball = __ballot_sync(0xffffffffu, pass);
    if (lane == 0) g_mask[tile] = ball;
}

// ---------------------------------------------------------------------------
// BEV kernel: grid (GX/32, GY, BATCH) = 1024 blocks, 512 threads.
//   warp (tid>>5) = channel group cg (channels cg*4..cg*4+3), cg in 0..15
//   lane (tid&31) = x within the block's 32-wide tile
// No smem, no barriers. Empty path = 1 uniform LDG (mask) + 4 stores.
// Heavy path: iterate set mask bits ascending (deterministic FP order);
// per-lane projection with M broadcast-loaded from g_M; trilinear gather.
// ---------------------------------------------------------------------------
__global__ void __launch_bounds__(512)
bev_kernel(const float* __restrict__ frustum, float* __restrict__ out) {
    const int tid = threadIdx.x;
    const int b   = blockIdx.z;
    const int y   = blockIdx.y;
    const int bx  = blockIdx.x;
    const int x0t = bx * 32;

    const int lane = tid & 31;
    const int cg   = tid >> 5;           // 0..15, 4 channels each

    float acc[4];
    acc[0] = acc[1] = acc[2] = acc[3] = 0.0f;

    const int tile = (b * GY + y) * NTILE + bx;
    unsigned mk = __ldg(&g_mask[tile]);

    if (mk) {
        const float4* f4 = (const float4*)frustum;
        const float gy = -47.625f + 0.75f * (float)y;
        const float gx = -47.625f + 0.75f * (float)(x0t + lane);

        #pragma unroll 1
        while (mk) {
            const int combo = __ffs(mk) - 1;   // ascending: deterministic order
            mk &= mk - 1;
            const int cam = combo >> 2;
            const int zz  = combo & 3;
            const float gz = -3.0f + 2.0f * (float)zz;
            const float* M = g_M + (b * NCAM + cam) * 12;
            const float u  = __ldg(M+0)*gx + __ldg(M+1)*gy + __ldg(M+2)*gz  + __ldg(M+3);
            const float v  = __ldg(M+4)*gx + __ldg(M+5)*gy + __ldg(M+6)*gz  + __ldg(M+7);
            const float d  = __ldg(M+8)*gx + __ldg(M+9)*gy + __ldg(M+10)*gz + __ldg(M+11);
            const float rd = 1.0f / d;
            const float ix = u * rd * (59.0f/60.0f);
            const float iy = v * rd * (27.0f/28.0f);
            const float iz = (d - 2.0f) * (47.0f/48.0f);
            const bool ok = (ix > -1.0f) && (ix < 60.0f)
                         && (iy > -1.0f) && (iy < 28.0f)
                         && (iz > -1.0f) && (iz < 48.0f);
            if (!ok) continue;

            const float fx0 = floorf(ix); const int ix0 = (int)fx0; const float fx = ix - fx0;
            const float fy0 = floorf(iy); const int iy0 = (int)fy0; const float fy = iy - fy0;
            const float fz0 = floorf(iz); const int iz0 = (int)fz0; const float fz = iz - fz0;

            const float wx0 = (ix0 >= 0)      ? (1.0f - fx) : 0.0f;
            const float wx1 = (ix0 <= WW - 2) ? fx          : 0.0f;
            const float wy0 = (iy0 >= 0)      ? (1.0f - fy) : 0.0f;
            const float wy1 = (iy0 <= HH - 2) ? fy          : 0.0f;
            const float wz0 = (iz0 >= 0)      ? (1.0f - fz) : 0.0f;
            const float wz1 = (iz0 <= DD - 2) ? fz          : 0.0f;

            const int base = (b * NCAM + cam) * (DD * HH * WW);  // pixel units

            #pragma unroll
            for (int dz = 0; dz < 2; dz++) {
                const float wz = dz ? wz1 : wz0;
                if (wz == 0.0f) continue;
                const int zoff = base + (iz0 + dz) * (HH * WW);
                #pragma unroll
                for (int dy = 0; dy < 2; dy++) {
                    const float wzy = wz * (dy ? wy1 : wy0);
                    if (wzy == 0.0f) continue;
                    const int yoff = zoff + (iy0 + dy) * WW;
                    #pragma unroll
                    for (int dx = 0; dx < 2; dx++) {
                        const float w = wzy * (dx ? wx1 : wx0);
                        if (w == 0.0f) continue;
                        const int pix = yoff + (ix0 + dx);
                        const float4 a = __ldg(f4 + (size_t)pix * (CC / 4) + cg);
                        acc[0] += w * a.x; acc[1] += w * a.y;
                        acc[2] += w * a.z; acc[3] += w * a.w;
                    }
                }
            }
        }
    }

    // ---- coalesced stores: out[b][c][y][x] ----
    const int xg = x0t + lane;
    size_t obase = (((size_t)b * CC + cg * 4) * GY + y) * GX + xg;
    #pragma unroll
    for (int j = 0; j < 4; j++) {
        out[obase + (size_t)j * (GY * GX)] = acc[j];
    }
}

extern "C" void kernel_launch(void* const* d_in, const int* in_sizes, int n_in,
                              void* d_out, int out_size) {
    const float* frustum = (const float*)d_in[0];
    const float* intr    = (const float*)d_in[1];
    const float* l2s     = (const float*)d_in[2];
    float* out = (float*)d_out;

    prep_kernel<<<64, 512>>>(intr, l2s);
    dim3 grid(NTILE, GY, BATCH);
    bev_kernel<<<grid, 512>>>(frustum, out);
}

// round 14
// speedup vs baseline: 1.2374x; 1.2374x over previous
#include <cuda_runtime.h>
#include <cstdint>

// Problem constants
#define BATCH 2
#define NCAM  6
#define DD    48
#define HH    28
#define WW    60
#define CC    64
#define GX    128
#define GY    128

// ---------------------------------------------------------------------------
// Single fused kernel. Grid: (GX/32, GY, BATCH) = 1024 blocks, 512 threads.
//
// Setup (warp 0 only, R10-validated):
//   - all 32 lanes redundantly compute M = K @ inv(l2s)[0:3,:]; lanes 0..5
//     write sm_M; lanes 0..23 run the exact divide-free interval test for
//     combo = lane; ballot -> 24-bit sm_mask.
//
// Heavy path (mask != 0), TRANSPOSED gather to kill L1 wavefront waste:
//   warp wid handles x = {2*wid, 2*wid+1}; half-warp h = one x;
//   lane's cq = lane&15 = channel quad (channels 4cq..4cq+3).
//   Each corner load: 16 lanes read the pixel's 64 floats contiguously
//   (256B = 2 cache lines per half-warp -> 4 wavefronts/LDG.128, vs 32
//   with x-per-lane). Accumulation order per (x,channel) identical to the
//   validated kernel. Padded smem transpose -> coalesced x-major stores.
//
// Empty path: no barrier beyond setup, store zeros.
// ---------------------------------------------------------------------------
__global__ void __launch_bounds__(512)
bev_kernel(const float* __restrict__ frustum,
           const float* __restrict__ intr,
           const float* __restrict__ l2s,
           float* __restrict__ out) {
    __shared__ float sm_M[NCAM * 12];
    __shared__ unsigned sm_mask;
    __shared__ float4 sm_t[32 * 17];   // [x][cq], stride 17 kills bank conflicts

    const int tid = threadIdx.x;
    const int b   = blockIdx.z;
    const int y   = blockIdx.y;
    const int x0t = blockIdx.x * 32;

    const float gy = -47.625f + 0.75f * (float)y;

    if (tid < 32) {
        const int lane = tid;
        // ---- inverse + M, computed by all lanes for cam = min(lane,5) ----
        const int camL = lane < 6 ? lane : 5;
        const int idx  = b * NCAM + camL;
        const float* m = l2s + idx * 16;   // row-major 4x4
        const float* K = intr + idx * 9;   // row-major 3x3

        float inv[16];
        inv[0]  =  m[5]*m[10]*m[15] - m[5]*m[11]*m[14] - m[9]*m[6]*m[15] + m[9]*m[7]*m[14] + m[13]*m[6]*m[11] - m[13]*m[7]*m[10];
        inv[4]  = -m[4]*m[10]*m[15] + m[4]*m[11]*m[14] + m[8]*m[6]*m[15] - m[8]*m[7]*m[14] - m[12]*m[6]*m[11] + m[12]*m[7]*m[10];
        inv[8]  =  m[4]*m[9]*m[15]  - m[4]*m[11]*m[13] - m[8]*m[5]*m[15] + m[8]*m[7]*m[13] + m[12]*m[5]*m[11] - m[12]*m[7]*m[9];
        inv[12] = -m[4]*m[9]*m[14]  + m[4]*m[10]*m[13] + m[8]*m[5]*m[14] - m[8]*m[6]*m[13] - m[12]*m[5]*m[10] + m[12]*m[6]*m[9];
        inv[1]  = -m[1]*m[10]*m[15] + m[1]*m[11]*m[14] + m[9]*m[2]*m[15] - m[9]*m[3]*m[14] - m[13]*m[2]*m[11] + m[13]*m[3]*m[10];
        inv[5]  =  m[0]*m[10]*m[15] - m[0]*m[11]*m[14] - m[8]*m[2]*m[15] + m[8]*m[3]*m[14] + m[12]*m[2]*m[11] - m[12]*m[3]*m[10];
        inv[9]  = -m[0]*m[9]*m[15]  + m[0]*m[11]*m[13] + m[8]*m[1]*m[15] - m[8]*m[3]*m[13] - m[12]*m[1]*m[11] + m[12]*m[3]*m[9];
        inv[13] =  m[0]*m[9]*m[14]  - m[0]*m[10]*m[13] - m[8]*m[1]*m[14] + m[8]*m[2]*m[13] + m[12]*m[1]*m[10] - m[12]*m[2]*m[9];
        inv[2]  =  m[1]*m[6]*m[15]  - m[1]*m[7]*m[14]  - m[5]*m[2]*m[15] + m[5]*m[3]*m[14] + m[13]*m[2]*m[7]  - m[13]*m[3]*m[6];
        inv[6]  = -m[0]*m[6]*m[15]  + m[0]*m[7]*m[14]  + m[4]*m[2]*m[15] - m[4]*m[3]*m[14] - m[12]*m[2]*m[7]  + m[12]*m[3]*m[6];
        inv[10] =  m[0]*m[5]*m[15]  - m[0]*m[7]*m[13]  - m[4]*m[1]*m[15] + m[4]*m[3]*m[13] + m[12]*m[1]*m[7]  - m[12]*m[3]*m[5];
        inv[14] = -m[0]*m[5]*m[14]  + m[0]*m[6]*m[13]  + m[4]*m[1]*m[14] - m[4]*m[2]*m[13] - m[12]*m[1]*m[6]  + m[12]*m[2]*m[5];
        inv[3]  = -m[1]*m[6]*m[11]  + m[1]*m[7]*m[10]  + m[5]*m[2]*m[11] - m[5]*m[3]*m[10] - m[9]*m[2]*m[7]   + m[9]*m[3]*m[6];
        inv[7]  =  m[0]*m[6]*m[11]  - m[0]*m[7]*m[10]  - m[4]*m[2]*m[11] + m[4]*m[3]*m[10] + m[8]*m[2]*m[7]   - m[8]*m[3]*m[6];
        inv[11] = -m[0]*m[5]*m[11]  + m[0]*m[7]*m[9]   + m[4]*m[1]*m[11] - m[4]*m[3]*m[9]  - m[8]*m[1]*m[7]   + m[8]*m[3]*m[5];
        inv[15] =  m[0]*m[5]*m[10]  - m[0]*m[6]*m[9]   - m[4]*m[1]*m[10] + m[4]*m[2]*m[9]  + m[8]*m[1]*m[6]   - m[8]*m[2]*m[5];

        float det = m[0]*inv[0] + m[1]*inv[4] + m[2]*inv[8] + m[3]*inv[12];
        float rdet = 1.0f / det;
        #pragma unroll
        for (int i = 0; i < 16; i++) inv[i] *= rdet;

        float Mr[12];
        #pragma unroll
        for (int r = 0; r < 3; r++) {
            #pragma unroll
            for (int c = 0; c < 4; c++) {
                Mr[r * 4 + c] = K[r*3 + 0] * inv[0*4 + c]
                              + K[r*3 + 1] * inv[1*4 + c]
                              + K[r*3 + 2] * inv[2*4 + c];
            }
        }
        if (lane < 6) {
            #pragma unroll
            for (int i = 0; i < 12; i++) sm_M[lane * 12 + i] = Mr[i];
        }

        // ---- exact divide-free interval test: lanes 0..23, combo = lane ----
        const int cam = lane >> 2;     // valid for lane < 24
        float Ms[12];
        #pragma unroll
        for (int i = 0; i < 12; i++)
            Ms[i] = __shfl_sync(0xffffffffu, Mr[i], cam < 6 ? cam : 0);

        int pass = 0;
        if (lane < 24) {
            const int zz  = lane & 3;
            const float gz  = -3.0f + 2.0f * (float)zz;
            const float gxa = -47.625f + 0.75f * (float)(x0t);
            const float gxb = -47.625f + 0.75f * (float)(x0t + 31);
            const float DLO = 0.9770f;   // d > 2 - 48/47, widened down
            const float DHI = 51.05f;    // d < 2 + 48*48/47, widened up
            const float uc = Ms[1]*gy + Ms[2]*gz  + Ms[3];
            const float vc = Ms[5]*gy + Ms[6]*gz  + Ms[7];
            const float dc = Ms[9]*gy + Ms[10]*gz + Ms[11];
            float u0 = Ms[0]*gxa + uc, u1 = Ms[0]*gxb + uc;
            float v0 = Ms[4]*gxa + vc, v1 = Ms[4]*gxb + vc;
            float d0 = Ms[8]*gxa + dc, d1 = Ms[8]*gxb + dc;
            const float dmin = fminf(d0, d1), dmax = fmaxf(d0, d1);
            if (dmax > DLO && dmin < DHI) {
                if (dmin < DLO) {
                    // d crosses DLO inside tile; affine => exact crossing.
                    const float t  = (DLO - d0) / (d1 - d0);
                    const float uX = u0 + t * (u1 - u0);
                    const float vX = v0 + t * (v1 - v0);
                    if (d0 < DLO) { u0 = uX; v0 = vX; d0 = DLO; }
                    else          { u1 = uX; v1 = vX; d1 = DLO; }
                }
                // d > 0 on (sub)interval: multiply bounds through by d.
                const float sx = 59.0f / 60.0f, sy = 27.0f / 28.0f;
                const float a0 = sx * u0, a1 = sx * u1;
                const float e0 = sy * v0, e1 = sy * v1;
                const bool rej =
                    (fmaxf(a0 + 1.002f  * d0, a1 + 1.002f  * d1) <= 0.0f) ||
                    (fminf(a0 - 60.002f * d0, a1 - 60.002f * d1) >= 0.0f) ||
                    (fmaxf(e0 + 1.002f  * d0, e1 + 1.002f  * d1) <= 0.0f) ||
                    (fminf(e0 - 28.002f * d0, e1 - 28.002f * d1) >= 0.0f);
                pass = !rej;
            }
        }
        const unsigned ball = __ballot_sync(0xffffffffu, pass);
        if (lane == 0) sm_mask = ball;
    }
    __syncthreads();

    const int lane = tid & 31;
    const int cg   = tid >> 5;           // warp id; also channel group for store

    float st0 = 0.0f, st1 = 0.0f, st2 = 0.0f, st3 = 0.0f;

    unsigned mk = sm_mask;               // block-uniform
    if (mk) {
        // ---- transposed gather: warp cg handles x = {2cg, 2cg+1} ----
        const int h  = lane >> 4;        // which x of the pair
        const int cq = lane & 15;        // channel quad: channels 4cq..4cq+3
        const int xl = cg * 2 + h;
        const float gx = -47.625f + 0.75f * (float)(x0t + xl);
        const float4* f4 = (const float4*)frustum;

        float a0 = 0.0f, a1 = 0.0f, a2 = 0.0f, a3 = 0.0f;

        #pragma unroll 1
        while (mk) {
            const int combo = __ffs(mk) - 1;   // ascending: deterministic order
            mk &= mk - 1;
            const int cam = combo >> 2;
            const int zz  = combo & 3;
            const float gz = -3.0f + 2.0f * (float)zz;
            const float* M = &sm_M[cam * 12];
            const float u  = M[0]*gx + M[1]*gy + M[2]*gz  + M[3];
            const float v  = M[4]*gx + M[5]*gy + M[6]*gz  + M[7];
            const float d  = M[8]*gx + M[9]*gy + M[10]*gz + M[11];
            const float rd = 1.0f / d;
            const float ix = u * rd * (59.0f/60.0f);
            const float iy = v * rd * (27.0f/28.0f);
            const float iz = (d - 2.0f) * (47.0f/48.0f);
            const bool ok = (ix > -1.0f) && (ix < 60.0f)
                         && (iy > -1.0f) && (iy < 28.0f)
                         && (iz > -1.0f) && (iz < 48.0f);
            if (ok) {
                const float fx0 = floorf(ix); const int ix0 = (int)fx0; const float fx = ix - fx0;
                const float fy0 = floorf(iy); const int iy0 = (int)fy0; const float fy = iy - fy0;
                const float fz0 = floorf(iz); const int iz0 = (int)fz0; const float fz = iz - fz0;

                const float wx0 = (ix0 >= 0)      ? (1.0f - fx) : 0.0f;
                const float wx1 = (ix0 <= WW - 2) ? fx          : 0.0f;
                const float wy0 = (iy0 >= 0)      ? (1.0f - fy) : 0.0f;
                const float wy1 = (iy0 <= HH - 2) ? fy          : 0.0f;
                const float wz0 = (iz0 >= 0)      ? (1.0f - fz) : 0.0f;
                const float wz1 = (iz0 <= DD - 2) ? fz          : 0.0f;

                const int base = (b * NCAM + cam) * (DD * HH * WW);  // pixels

                #pragma unroll
                for (int dz = 0; dz < 2; dz++) {
                    const float wz = dz ? wz1 : wz0;
                    if (wz == 0.0f) continue;
                    const int zoff = base + (iz0 + dz) * (HH * WW);
                    #pragma unroll
                    for (int dy = 0; dy < 2; dy++) {
                        const float wzy = wz * (dy ? wy1 : wy0);
                        if (wzy == 0.0f) continue;
                        const int yoff = zoff + (iy0 + dy) * WW;
                        #pragma unroll
                        for (int dx = 0; dx < 2; dx++) {
                            const float w = wzy * (dx ? wx1 : wx0);
                            if (w == 0.0f) continue;
                            const int pix = yoff + (ix0 + dx);
                            // 16 lanes read this pixel's 64 channels
                            // contiguously: 256B per half-warp.
                            const float4 a = __ldg(f4 + (size_t)pix * (CC / 4) + cq);
                            a0 += w * a.x; a1 += w * a.y;
                            a2 += w * a.z; a3 += w * a.w;
                        }
                    }
                }
            }
        }

        // ---- smem transpose: [x][cq] -> read as [lane=x][cg] ----
        sm_t[xl * 17 + cq] = make_float4(a0, a1, a2, a3);
        __syncthreads();                    // uniform: mk was block-uniform
        const float4 vv = sm_t[lane * 17 + cg];
        st0 = vv.x; st1 = vv.y; st2 = vv.z; st3 = vv.w;
    }

    // ---- coalesced stores: out[b][c][y][x], c = cg*4+j, x = x0t+lane ----
    const int xg = x0t + lane;
    size_t obase = (((size_t)b * CC + cg * 4) * GY + y) * GX + xg;
    out[obase]                      = st0;
    out[obase + (size_t)(GY * GX)]  = st1;
    out[obase + (size_t)(2*GY*GX)]  = st2;
    out[obase + (size_t)(3*GY*GX)]  = st3;
}

extern "C" void kernel_launch(void* const* d_in, const int* in_sizes, int n_in,
                              void* d_out, int out_size) {
    const float* frustum = (const float*)d_in[0];
    const float* intr    = (const float*)d_in[1];
    const float* l2s     = (const float*)d_in[2];
    float* out = (float*)d_out;

    dim3 grid(GX / 32, GY, BATCH);
    bev_kernel<<<grid, 512>>>(frustum, intr, l2s, out);
}

// round 15
// speedup vs baseline: 1.2562x; 1.0152x over previous
#include <cuda_runtime.h>
#include <cstdint>

// Problem constants
#define BATCH 2
#define NCAM  6
#define DD    48
#define HH    28
#define WW    60
#define CC    64
#define GX    128
#define GY    128

// ---------------------------------------------------------------------------
// Single fused kernel. Grid: (GX/32, GY, BATCH) = 1024 blocks, 1024 threads.
//   wid = tid>>5 (0..31); cg = wid&15 (channel group, 4 ch/thread);
//   g = wid>>4 (combo-parity group); lane = x within the 32-wide tile.
//
// Setup (warp 0 only, validated R10/R14):
//   - all 32 lanes redundantly compute M = K @ inv(l2s)[0:3,:]; lanes 0..5
//     write sm_M; lanes 0..23 run the exact divide-free interval test for
//     combo = lane; ballot -> mask; lanes with pass compact their combo id
//     into sm_list (ascending, deterministic).
//
// Heavy path: warp group g processes list positions k = g, g+2, ... (per-warp
// serial chain halved vs one group). #pragma unroll 2 lets the compiler
// overlap next combo's loads with current accumulate. Group 1 partials are
// added to group 0 via an smem buffer; summation order is (even positions
// ascending) + (odd positions ascending) — fixed and deterministic.
//
// Stores: warps 0..15, coalesced x-major, out[b][c][y][x].
// ---------------------------------------------------------------------------
__global__ void __launch_bounds__(1024)
bev_kernel(const float* __restrict__ frustum,
           const float* __restrict__ intr,
           const float* __restrict__ l2s,
           float* __restrict__ out) {
    __shared__ float sm_M[NCAM * 12];
    __shared__ unsigned sm_mask;
    __shared__ unsigned char sm_list[24];
    __shared__ float4 sm_part[16][32];   // [cg][lane] group-1 partials (8 KB)

    const int tid = threadIdx.x;
    const int b   = blockIdx.z;
    const int y   = blockIdx.y;
    const int x0t = blockIdx.x * 32;

    const float gy = -47.625f + 0.75f * (float)y;

    if (tid < 32) {
        const int lane = tid;
        // ---- inverse + M, computed by all lanes for cam = min(lane,5) ----
        const int camL = lane < 6 ? lane : 5;
        const int idx  = b * NCAM + camL;
        const float* m = l2s + idx * 16;   // row-major 4x4
        const float* K = intr + idx * 9;   // row-major 3x3

        float inv[16];
        inv[0]  =  m[5]*m[10]*m[15] - m[5]*m[11]*m[14] - m[9]*m[6]*m[15] + m[9]*m[7]*m[14] + m[13]*m[6]*m[11] - m[13]*m[7]*m[10];
        inv[4]  = -m[4]*m[10]*m[15] + m[4]*m[11]*m[14] + m[8]*m[6]*m[15] - m[8]*m[7]*m[14] - m[12]*m[6]*m[11] + m[12]*m[7]*m[10];
        inv[8]  =  m[4]*m[9]*m[15]  - m[4]*m[11]*m[13] - m[8]*m[5]*m[15] + m[8]*m[7]*m[13] + m[12]*m[5]*m[11] - m[12]*m[7]*m[9];
        inv[12] = -m[4]*m[9]*m[14]  + m[4]*m[10]*m[13] + m[8]*m[5]*m[14] - m[8]*m[6]*m[13] - m[12]*m[5]*m[10] + m[12]*m[6]*m[9];
        inv[1]  = -m[1]*m[10]*m[15] + m[1]*m[11]*m[14] + m[9]*m[2]*m[15] - m[9]*m[3]*m[14] - m[13]*m[2]*m[11] + m[13]*m[3]*m[10];
        inv[5]  =  m[0]*m[10]*m[15] - m[0]*m[11]*m[14] - m[8]*m[2]*m[15] + m[8]*m[3]*m[14] + m[12]*m[2]*m[11] - m[12]*m[3]*m[10];
        inv[9]  = -m[0]*m[9]*m[15]  + m[0]*m[11]*m[13] + m[8]*m[1]*m[15] - m[8]*m[3]*m[13] - m[12]*m[1]*m[11] + m[12]*m[3]*m[9];
        inv[13] =  m[0]*m[9]*m[14]  - m[0]*m[10]*m[13] - m[8]*m[1]*m[14] + m[8]*m[2]*m[13] + m[12]*m[1]*m[10] - m[12]*m[2]*m[9];
        inv[2]  =  m[1]*m[6]*m[15]  - m[1]*m[7]*m[14]  - m[5]*m[2]*m[15] + m[5]*m[3]*m[14] + m[13]*m[2]*m[7]  - m[13]*m[3]*m[6];
        inv[6]  = -m[0]*m[6]*m[15]  + m[0]*m[7]*m[14]  + m[4]*m[2]*m[15] - m[4]*m[3]*m[14] - m[12]*m[2]*m[7]  + m[12]*m[3]*m[6];
        inv[10] =  m[0]*m[5]*m[15]  - m[0]*m[7]*m[13]  - m[4]*m[1]*m[15] + m[4]*m[3]*m[13] + m[12]*m[1]*m[7]  - m[12]*m[3]*m[5];
        inv[14] = -m[0]*m[5]*m[14]  + m[0]*m[6]*m[13]  + m[4]*m[1]*m[14] - m[4]*m[2]*m[13] - m[12]*m[1]*m[6]  + m[12]*m[2]*m[5];
        inv[3]  = -m[1]*m[6]*m[11]  + m[1]*m[7]*m[10]  + m[5]*m[2]*m[11] - m[5]*m[3]*m[10] - m[9]*m[2]*m[7]   + m[9]*m[3]*m[6];
        inv[7]  =  m[0]*m[6]*m[11]  - m[0]*m[7]*m[10]  - m[4]*m[2]*m[11] + m[4]*m[3]*m[10] + m[8]*m[2]*m[7]   - m[8]*m[3]*m[6];
        inv[11] = -m[0]*m[5]*m[11]  + m[0]*m[7]*m[9]   + m[4]*m[1]*m[11] - m[4]*m[3]*m[9]  - m[8]*m[1]*m[7]   + m[8]*m[3]*m[5];
        inv[15] =  m[0]*m[5]*m[10]  - m[0]*m[6]*m[9]   - m[4]*m[1]*m[10] + m[4]*m[2]*m[9]  + m[8]*m[1]*m[6]   - m[8]*m[2]*m[5];

        float det = m[0]*inv[0] + m[1]*inv[4] + m[2]*inv[8] + m[3]*inv[12];
        float rdet = 1.0f / det;
        #pragma unroll
        for (int i = 0; i < 16; i++) inv[i] *= rdet;

        float Mr[12];
        #pragma unroll
        for (int r = 0; r < 3; r++) {
            #pragma unroll
            for (int c = 0; c < 4; c++) {
                Mr[r * 4 + c] = K[r*3 + 0] * inv[0*4 + c]
                              + K[r*3 + 1] * inv[1*4 + c]
                              + K[r*3 + 2] * inv[2*4 + c];
            }
        }
        if (lane < 6) {
            #pragma unroll
            for (int i = 0; i < 12; i++) sm_M[lane * 12 + i] = Mr[i];
        }

        // ---- exact divide-free interval test: lanes 0..23, combo = lane ----
        const int cam = lane >> 2;     // valid for lane < 24
        float Ms[12];
        #pragma unroll
        for (int i = 0; i < 12; i++)
            Ms[i] = __shfl_sync(0xffffffffu, Mr[i], cam < 6 ? cam : 0);

        int pass = 0;
        if (lane < 24) {
            const int zz  = lane & 3;
            const float gz  = -3.0f + 2.0f * (float)zz;
            const float gxa = -47.625f + 0.75f * (float)(x0t);
            const float gxb = -47.625f + 0.75f * (float)(x0t + 31);
            const float DLO = 0.9770f;   // d > 2 - 48/47, widened down
            const float DHI = 51.05f;    // d < 2 + 48*48/47, widened up
            const float uc = Ms[1]*gy + Ms[2]*gz  + Ms[3];
            const float vc = Ms[5]*gy + Ms[6]*gz  + Ms[7];
            const float dc = Ms[9]*gy + Ms[10]*gz + Ms[11];
            float u0 = Ms[0]*gxa + uc, u1 = Ms[0]*gxb + uc;
            float v0 = Ms[4]*gxa + vc, v1 = Ms[4]*gxb + vc;
            float d0 = Ms[8]*gxa + dc, d1 = Ms[8]*gxb + dc;
            const float dmin = fminf(d0, d1), dmax = fmaxf(d0, d1);
            if (dmax > DLO && dmin < DHI) {
                if (dmin < DLO) {
                    // d crosses DLO inside tile; affine => exact crossing.
                    const float t  = (DLO - d0) / (d1 - d0);
                    const float uX = u0 + t * (u1 - u0);
                    const float vX = v0 + t * (v1 - v0);
                    if (d0 < DLO) { u0 = uX; v0 = vX; d0 = DLO; }
                    else          { u1 = uX; v1 = vX; d1 = DLO; }
                }
                // d > 0 on (sub)interval: multiply bounds through by d.
                const float sx = 59.0f / 60.0f, sy = 27.0f / 28.0f;
                const float a0 = sx * u0, a1 = sx * u1;
                const float e0 = sy * v0, e1 = sy * v1;
                const bool rej =
                    (fmaxf(a0 + 1.002f  * d0, a1 + 1.002f  * d1) <= 0.0f) ||
                    (fminf(a0 - 60.002f * d0, a1 - 60.002f * d1) >= 0.0f) ||
                    (fmaxf(e0 + 1.002f  * d0, e1 + 1.002f  * d1) <= 0.0f) ||
                    (fminf(e0 - 28.002f * d0, e1 - 28.002f * d1) >= 0.0f);
                pass = !rej;
            }
        }
        const unsigned ball = __ballot_sync(0xffffffffu, pass);
        if (pass) {
            const int pos = __popc(ball & ((1u << lane) - 1u));
            sm_list[pos] = (unsigned char)lane;   // ascending combo order
        }
        if (lane == 0) sm_mask = ball;
    }
    __syncthreads();

    const int lane = tid & 31;
    const int wid  = tid >> 5;
    const int cg   = wid & 15;           // channel group: channels 4cg..4cg+3
    const int g    = wid >> 4;           // combo-parity group

    float a0 = 0.0f, a1 = 0.0f, a2 = 0.0f, a3 = 0.0f;

    const int cnt = __popc(sm_mask);     // block-uniform
    if (cnt) {
        const float4* f4 = (const float4*)frustum;
        const float gx = -47.625f + 0.75f * (float)(x0t + lane);

        // ---- gather-accumulate: group g takes list positions g, g+2, ... ----
        #pragma unroll 2
        for (int k = g; k < cnt; k += 2) {
            const int combo = (int)sm_list[k];
            const int cam = combo >> 2;
            const int zz  = combo & 3;
            const float gz = -3.0f + 2.0f * (float)zz;
            const float* M = &sm_M[cam * 12];
            const float u  = M[0]*gx + M[1]*gy + M[2]*gz  + M[3];
            const float v  = M[4]*gx + M[5]*gy + M[6]*gz  + M[7];
            const float d  = M[8]*gx + M[9]*gy + M[10]*gz + M[11];
            const float rd = 1.0f / d;
            const float ix = u * rd * (59.0f/60.0f);
            const float iy = v * rd * (27.0f/28.0f);
            const float iz = (d - 2.0f) * (47.0f/48.0f);
            const bool ok = (ix > -1.0f) && (ix < 60.0f)
                         && (iy > -1.0f) && (iy < 28.0f)
                         && (iz > -1.0f) && (iz < 48.0f);
            if (!ok) continue;

            const float fx0 = floorf(ix); const int ix0 = (int)fx0; const float fx = ix - fx0;
            const float fy0 = floorf(iy); const int iy0 = (int)fy0; const float fy = iy - fy0;
            const float fz0 = floorf(iz); const int iz0 = (int)fz0; const float fz = iz - fz0;

            const float wx0 = (ix0 >= 0)      ? (1.0f - fx) : 0.0f;
            const float wx1 = (ix0 <= WW - 2) ? fx          : 0.0f;
            const float wy0 = (iy0 >= 0)      ? (1.0f - fy) : 0.0f;
            const float wy1 = (iy0 <= HH - 2) ? fy          : 0.0f;
            const float wz0 = (iz0 >= 0)      ? (1.0f - fz) : 0.0f;
            const float wz1 = (iz0 <= DD - 2) ? fz          : 0.0f;

            const int base = (b * NCAM + cam) * (DD * HH * WW);  // pixel units

            #pragma unroll
            for (int dz = 0; dz < 2; dz++) {
                const float wz = dz ? wz1 : wz0;
                if (wz == 0.0f) continue;
                const int zoff = base + (iz0 + dz) * (HH * WW);
                #pragma unroll
                for (int dy = 0; dy < 2; dy++) {
                    const float wzy = wz * (dy ? wy1 : wy0);
                    if (wzy == 0.0f) continue;
                    const int yoff = zoff + (iy0 + dy) * WW;
                    #pragma unroll
                    for (int dx = 0; dx < 2; dx++) {
                        const float w = wzy * (dx ? wx1 : wx0);
                        if (w == 0.0f) continue;
                        const int pix = yoff + (ix0 + dx);
                        const float4 a = __ldg(f4 + (size_t)pix * (CC / 4) + cg);
                        a0 += w * a.x; a1 += w * a.y;
                        a2 += w * a.z; a3 += w * a.w;
                    }
                }
            }
        }

        // ---- combine group-1 partials into group 0 ----
        if (g) sm_part[cg][lane] = make_float4(a0, a1, a2, a3);
        __syncthreads();                 // block-uniform (cnt uniform)
        if (!g) {
            const float4 p = sm_part[cg][lane];
            a0 += p.x; a1 += p.y; a2 += p.z; a3 += p.w;
        }
    }

    // ---- coalesced stores (warps 0..15): out[b][c][y][x] ----
    if (!g) {
        const int xg = x0t + lane;
        size_t obase = (((size_t)b * CC + cg * 4) * GY + y) * GX + xg;
        out[obase]                      = a0;
        out[obase + (size_t)(GY * GX)]  = a1;
        out[obase + (size_t)(2*GY*GX)]  = a2;
        out[obase + (size_t)(3*GY*GX)]  = a3;
    }
}

extern "C" void kernel_launch(void* const* d_in, const int* in_sizes, int n_in,
                              void* d_out, int out_size) {
    const float* frustum = (const float*)d_in[0];
    const float* intr    = (const float*)d_in[1];
    const float* l2s     = (const float*)d_in[2];
    float* out = (float*)d_out;

    dim3 grid(GX / 32, GY, BATCH);
    bev_kernel<<<grid, 1024>>>(frustum, intr, l2s, out);
}